// round 1
// baseline (speedup 1.0000x reference)
#include <cuda_runtime.h>
#include <math.h>

#define B_ 64
#define T_ 2048
#define I_ 64
#define S_ 128
#define O_ 64
#define LN_EPS 1e-5f
#define NSEG 8
#define SEGT (T_/NSEG)

typedef unsigned long long ull;

// ------------- device scratch (no allocs allowed) -------------
__device__ float g_G [B_*T_*S_];   // sigmoid gates
__device__ float g_XB[B_*T_*S_];   // x @ B^T
__device__ float g_H [B_*T_*S_];   // normalized hidden states
__device__ float g_boSum[B_*O_];
__device__ float g_boSsq[B_*O_];
__device__ float g_S1;   // sum of diff norms
__device__ float g_S2;   // sum of norms
__device__ float g_SA;   // sum of sigmoids (selection activity)

// ------------- f32x2 helpers (Blackwell packed FMA) -------------
__device__ __forceinline__ ull pack2(float lo, float hi) {
    ull r; asm("mov.b64 %0,{%1,%2};" : "=l"(r) : "f"(lo), "f"(hi)); return r;
}
__device__ __forceinline__ void unpack2(ull v, float &lo, float &hi) {
    asm("mov.b64 {%0,%1},%2;" : "=f"(lo), "=f"(hi) : "l"(v));
}
__device__ __forceinline__ ull ffma2(ull a, ull b, ull c) {
    ull d; asm("fma.rn.f32x2 %0,%1,%2,%3;" : "=l"(d) : "l"(a), "l"(b), "l"(c)); return d;
}

// ------------- zero accumulators -------------
__global__ void zeroK() {
    int i = blockIdx.x * blockDim.x + threadIdx.x;
    if (i < B_*O_) { g_boSum[i] = 0.f; g_boSsq[i] = 0.f; }
    if (i == 0) { g_S1 = 0.f; g_S2 = 0.f; g_SA = 0.f; }
}

// ------------- kernel 1: precompute gates and x@B^T -------------
// grid 512 blocks x 256 threads; each block handles 256 (b,t) rows.
// threads 0..127 compute gate row (Wsel), 128..255 compute XB row (Bm).
__global__ __launch_bounds__(256) void gateK(
    const float* __restrict__ x, const float* __restrict__ Wsel,
    const float* __restrict__ bsel, const float* __restrict__ Bm)
{
    __shared__ __align__(16) float xs[4][I_];
    int tid = threadIdx.x;
    bool isG = tid < S_;
    int s = isG ? tid : tid - S_;
    const float* wrow = isG ? (Wsel + s*I_) : (Bm + s*I_);
    ull w2[I_/2];
#pragma unroll
    for (int k = 0; k < I_/2; k++) w2[k] = pack2(wrow[2*k], wrow[2*k+1]);
    float bias = isG ? bsel[s] : 0.f;
    int row0 = blockIdx.x * 256;
    for (int g = 0; g < 256; g += 4) {
        {
            int r = tid >> 6, i = tid & 63;
            xs[r][i] = x[(row0 + g + r)*I_ + i];
        }
        __syncthreads();
#pragma unroll
        for (int r = 0; r < 4; r++) {
            const ull* xv = (const ull*)xs[r];
            ull a0 = 0, a1 = 0, a2 = 0, a3 = 0;
#pragma unroll
            for (int k = 0; k < I_/2; k += 4) {
                a0 = ffma2(w2[k+0], xv[k+0], a0);
                a1 = ffma2(w2[k+1], xv[k+1], a1);
                a2 = ffma2(w2[k+2], xv[k+2], a2);
                a3 = ffma2(w2[k+3], xv[k+3], a3);
            }
            float p,q,u,v,e,f,m,n;
            unpack2(a0,p,q); unpack2(a1,u,v); unpack2(a2,e,f); unpack2(a3,m,n);
            float dot = ((p+q)+(u+v)) + ((e+f)+(m+n));
            int row = row0 + g + r;
            if (isG) {
                float z = dot + bias;
                g_G[row*S_ + s] = 1.f / (1.f + __expf(-z));
            } else {
                g_XB[row*S_ + s] = dot;
            }
        }
        __syncthreads();
    }
}

// ------------- kernel 2: sequential recurrence, one CTA per batch -------------
// Lazy-LN trick: A is pre-scaled by gamma; dot runs on raw blended state hb,
// LN statistics (concurrent shfl reduce) enter as scalar corrections.
__global__ __launch_bounds__(128, 1) void recK(
    const float* __restrict__ A, const float* __restrict__ gamma,
    const float* __restrict__ beta)
{
    __shared__ __align__(16) float hbuf[2][S_];
    __shared__ float2 red[4];
    int s = threadIdx.x;
    int b = blockIdx.x;
    int lane = s & 31, warp = s >> 5;

    // A row folded with gamma; constant correction terms
    ull a2[S_/2];
    float agsum = 0.f, ab = 0.f;
    const float* arow = A + s*S_;
#pragma unroll
    for (int k = 0; k < S_/2; k++) {
        float g0 = gamma[2*k], g1 = gamma[2*k+1];
        float v0 = arow[2*k]*g0, v1 = arow[2*k+1]*g1;
        a2[k] = pack2(v0, v1);
        agsum += v0 + v1;
        ab += arow[2*k]*beta[2*k] + arow[2*k+1]*beta[2*k+1];
    }
    float gam_s = gamma[s], bet_s = beta[s];

    hbuf[0][s] = 0.f; hbuf[1][s] = 0.f;
    float hbmine = 0.f;

    const float* Gp  = g_G  + b*T_*S_ + s;
    const float* XBp = g_XB + b*T_*S_ + s;
    float*       Hp  = g_H  + b*T_*S_ + s;

    float gb[4], xb[4];
#pragma unroll
    for (int j = 0; j < 4; j++) { gb[j] = Gp[j*S_]; xb[j] = XBp[j*S_]; }
    __syncthreads();

    int cur = 0;
#pragma unroll 4
    for (int t = 0; t < T_; t++) {
        int slot = t & 3;
        float g = gb[slot], xbv = xb[slot];
        int tp = (t + 4 < T_) ? (t + 4) : (T_ - 1);
        gb[slot] = Gp[tp*S_]; xb[slot] = XBp[tp*S_];

        // concurrent reduction of previous hb (sum, sumsq)
        float s1 = hbmine, s2 = hbmine*hbmine;
#pragma unroll
        for (int off = 16; off > 0; off >>= 1) {
            s1 += __shfl_xor_sync(0xffffffffu, s1, off);
            s2 += __shfl_xor_sync(0xffffffffu, s2, off);
        }
        if (lane == 0) red[warp] = make_float2(s1, s2);

        // dot over raw hb with gamma-folded A
        const ulonglong2* hv = (const ulonglong2*)hbuf[cur];
        ull ac0 = 0, ac1 = 0, ac2 = 0, ac3 = 0;
#pragma unroll
        for (int j = 0; j < S_/4; j += 2) {
            ulonglong2 p = hv[j], q = hv[j+1];
            ac0 = ffma2(a2[2*j+0], p.x, ac0);
            ac1 = ffma2(a2[2*j+1], p.y, ac1);
            ac2 = ffma2(a2[2*j+2], q.x, ac2);
            ac3 = ffma2(a2[2*j+3], q.y, ac3);
        }
        __syncthreads();

        float2 r0 = red[0], r1 = red[1], r2 = red[2], r3 = red[3];
        float sum = (r0.x + r1.x) + (r2.x + r3.x);
        float ssq = (r0.y + r1.y) + (r2.y + r3.y);
        float mu  = sum * (1.f/S_);
        float var = ssq * (1.f/S_) - mu*mu;
        float rin = rsqrtf(var + LN_EPS);

        float hpn;
        if (t > 0) {
            hpn = (hbmine - mu)*rin*gam_s + bet_s;
            Hp[(t-1)*S_] = hpn;            // normalized h_{t-1}
        } else hpn = 0.f;

        float p0,p1,p2,p3,p4,p5,p6,p7;
        unpack2(ac0,p0,p1); unpack2(ac1,p2,p3); unpack2(ac2,p4,p5); unpack2(ac3,p6,p7);
        float dotAg = ((p0+p1)+(p2+p3)) + ((p4+p5)+(p6+p7));
        float abterm = (t > 0) ? ab : 0.f;
        float nextraw = rin*(dotAg - mu*agsum) + abterm + xbv;  // = LN(h_{t-1})@A^T + xb
        float hbnew = g*nextraw + (1.f - g)*hpn;

        hbmine = hbnew;
        hbuf[cur ^ 1][s] = hbnew;
        __syncthreads();
        cur ^= 1;
    }

    // epilogue: normalize and store the final state h_{T-1}
    float s1 = hbmine, s2 = hbmine*hbmine;
#pragma unroll
    for (int off = 16; off > 0; off >>= 1) {
        s1 += __shfl_xor_sync(0xffffffffu, s1, off);
        s2 += __shfl_xor_sync(0xffffffffu, s2, off);
    }
    if (lane == 0) red[warp] = make_float2(s1, s2);
    __syncthreads();
    float2 q0 = red[0], q1 = red[1], q2 = red[2], q3 = red[3];
    float sum = (q0.x + q1.x) + (q2.x + q3.x);
    float ssq = (q0.y + q1.y) + (q2.y + q3.y);
    float mu  = sum * (1.f/S_);
    float var = ssq * (1.f/S_) - mu*mu;
    float rin = rsqrtf(var + LN_EPS);
    Hp[(T_-1)*S_] = (hbmine - mu)*rin*gam_s + bet_s;
}

// ------------- selection activity -------------
__global__ __launch_bounds__(128) void selK(
    const float* __restrict__ x, const float* __restrict__ Wsel,
    const float* __restrict__ bsel)
{
    __shared__ float xm2[2][I_];
    __shared__ float part[4];
    int tid = threadIdx.x, b = blockIdx.x;
    int i = tid & 63, half = tid >> 6;
    const float* xp = x + ((size_t)b*T_ + half*(T_/2))*I_ + i;
    float a0=0,a1=0,a2=0,a3=0;
    for (int t = 0; t < T_/2; t += 4) {
        a0 += xp[(t+0)*I_]; a1 += xp[(t+1)*I_];
        a2 += xp[(t+2)*I_]; a3 += xp[(t+3)*I_];
    }
    xm2[half][i] = (a0+a1)+(a2+a3);
    __syncthreads();
    float acc = bsel[tid];
    const float* w = Wsel + tid*I_;
    const float invT = 1.0f/(float)T_;
#pragma unroll 8
    for (int k = 0; k < I_; k++) acc += (xm2[0][k] + xm2[1][k]) * invT * w[k];
    float sg = 1.f/(1.f + __expf(-acc));
#pragma unroll
    for (int off = 16; off > 0; off >>= 1) sg += __shfl_xor_sync(0xffffffffu, sg, off);
    if ((tid & 31) == 0) part[tid >> 5] = sg;
    __syncthreads();
    if (tid == 0) atomicAdd(&g_SA, (part[0]+part[1]) + (part[2]+part[3]));
}

// ------------- kernel 3: Y = H@C^T + x@D^T plus statistics -------------
// grid (B_*NSEG) x 256 threads; dynamic smem.
__global__ void outK(const float* __restrict__ x, const float* __restrict__ C,
                     const float* __restrict__ D, float* __restrict__ out)
{
    extern __shared__ __align__(16) char smraw[];
    ull*   Cp = (ull*)smraw;            // [64][64] pairs along s
    ull*   Dp = Cp + 64*64;             // [32][64] pairs along i
    float* Hs = (float*)(Dp + 32*64);   // [4][128]
    float* xs = Hs + 4*128;             // [4][64]
    float* Ys = xs + 4*64;              // [4][64]
    float* yp = Ys + 4*64;              // [64] previous row

    int tid = threadIdx.x;
    int b = blockIdx.x >> 3;
    int seg = blockIdx.x & 7;
    int tl = tid >> 6, o = tid & 63;
    int t0 = seg * SEGT;

    for (int idx = tid; idx < 64*64; idx += 256) {
        int k = idx >> 6, oo = idx & 63;
        Cp[idx] = pack2(C[oo*S_ + 2*k], C[oo*S_ + 2*k + 1]);
    }
    for (int idx = tid; idx < 32*64; idx += 256) {
        int k = idx >> 6, oo = idx & 63;
        Dp[idx] = pack2(D[oo*I_ + 2*k], D[oo*I_ + 2*k + 1]);
    }
    if (tid < 64) yp[tid] = 0.f;
    __syncthreads();

    // boundary row t0-1 (recomputed so diffs cross segment borders)
    if (seg > 0) {
        if (tid < 128) Hs[tid] = g_H[((size_t)b*T_ + (t0-1))*S_ + tid];
        if (tid >= 128 && tid < 192) xs[tid-128] = x[((size_t)b*T_ + (t0-1))*I_ + (tid-128)];
        __syncthreads();
        if (tid < 64) {
            const ull* hv = (const ull*)Hs;
            ull ac0 = 0, ac1 = 0;
#pragma unroll
            for (int k = 0; k < 64; k += 2) {
                ac0 = ffma2(hv[k],   Cp[k*64 + tid],     ac0);
                ac1 = ffma2(hv[k+1], Cp[(k+1)*64 + tid], ac1);
            }
            const ull* xv = (const ull*)xs;
#pragma unroll
            for (int k = 0; k < 32; k += 2) {
                ac0 = ffma2(xv[k],   Dp[k*64 + tid],     ac0);
                ac1 = ffma2(xv[k+1], Dp[(k+1)*64 + tid], ac1);
            }
            float u,v,e,f; unpack2(ac0,u,v); unpack2(ac1,e,f);
            yp[tid] = (u+v)+(e+f);
        }
    }
    __syncthreads();

    float boS = 0.f, boQ = 0.f;       // per-(b,o) partials over this thread's t's
    float nrmAcc = 0.f, difAcc = 0.f; // only meaningful on (warp<4, lane0)
    int w = tid >> 5, lane = tid & 31;

    for (int g = 0; g < SEGT/4; g++) {
        int tbase = t0 + g*4;
        Hs[tid]       = g_H[((size_t)b*T_ + tbase + (tid >> 7))    *S_ + (tid & 127)];
        Hs[tid + 256] = g_H[((size_t)b*T_ + tbase + 2 + (tid >> 7))*S_ + (tid & 127)];
        xs[tid]       = x  [((size_t)b*T_ + tbase + (tid >> 6))    *I_ + (tid & 63)];
        __syncthreads();

        float y;
        {
            const ull* hv = (const ull*)(Hs + tl*128);
            ull ac0 = 0, ac1 = 0;
#pragma unroll
            for (int k = 0; k < 64; k += 2) {
                ac0 = ffma2(hv[k],   Cp[k*64 + o],     ac0);
                ac1 = ffma2(hv[k+1], Cp[(k+1)*64 + o], ac1);
            }
            const ull* xv = (const ull*)(xs + tl*64);
#pragma unroll
            for (int k = 0; k < 32; k += 2) {
                ac0 = ffma2(xv[k],   Dp[k*64 + o],     ac0);
                ac1 = ffma2(xv[k+1], Dp[(k+1)*64 + o], ac1);
            }
            float u,v,e,f; unpack2(ac0,u,v); unpack2(ac1,e,f);
            y = (u+v)+(e+f);
        }
        Ys[tl*64 + o] = y;
        boS += y; boQ += y*y;
        if (tbase + tl == T_ - 1) out[b*O_ + o] = y;   // final[b, o]
        __syncthreads();

        if (w < 4) {   // warps 0..3 reduce row norms and diff norms
            float y0 = Ys[w*64 + lane], y1 = Ys[w*64 + lane + 32];
            float p0, p1;
            if (w == 0) { p0 = yp[lane]; p1 = yp[lane + 32]; }
            else        { p0 = Ys[(w-1)*64 + lane]; p1 = Ys[(w-1)*64 + lane + 32]; }
            float sn = y0*y0 + y1*y1;
            float d0 = y0 - p0, d1 = y1 - p1;
            float dn = d0*d0 + d1*d1;
#pragma unroll
            for (int off = 16; off > 0; off >>= 1) {
                sn += __shfl_xor_sync(0xffffffffu, sn, off);
                dn += __shfl_xor_sync(0xffffffffu, dn, off);
            }
            if (lane == 0) {
                nrmAcc += sqrtf(sn);
                if (tbase + w > 0) difAcc += sqrtf(dn);
            }
        }
        __syncthreads();
        if (tid < 64) yp[tid] = Ys[3*64 + tid];
        __syncthreads();
    }

    if (w < 4 && lane == 0) {
        atomicAdd(&g_S2, nrmAcc);
        atomicAdd(&g_S1, difAcc);
    }
    // combine per-(b,o) partials across the 4 tl groups
    __syncthreads();
    Ys[tid] = boS;
    __syncthreads();
    if (tl == 0) atomicAdd(&g_boSum[b*64 + o], (Ys[o] + Ys[64+o]) + (Ys[128+o] + Ys[192+o]));
    __syncthreads();
    Ys[tid] = boQ;
    __syncthreads();
    if (tl == 0) atomicAdd(&g_boSsq[b*64 + o], (Ys[o] + Ys[64+o]) + (Ys[128+o] + Ys[192+o]));
}

// ------------- finalize scalars -------------
__global__ void finK(float* __restrict__ out)
{
    __shared__ float part[8];
    int tid = threadIdx.x;
    float acc = 0.f;
    for (int idx = tid; idx < B_*O_; idx += 256) {
        float sum = g_boSum[idx], ssq = g_boSsq[idx];
        float var = (ssq - sum*sum*(1.f/T_)) * (1.f/(T_ - 1));
        acc += sqrtf(fmaxf(var, 0.f));
    }
#pragma unroll
    for (int off = 16; off > 0; off >>= 1) acc += __shfl_xor_sync(0xffffffffu, acc, off);
    if ((tid & 31) == 0) part[tid >> 5] = acc;
    __syncthreads();
    if (tid == 0) {
        float tot = 0.f;
#pragma unroll
        for (int k = 0; k < 8; k++) tot += part[k];
        out[4096] = 1.f / (1.f + g_S1 / (float)(B_*(T_-1)));
        out[4097] = g_S2 / (float)(B_*T_);
        out[4098] = g_SA / (float)(B_*S_);
        out[4099] = tot  / (float)(B_*O_);
    }
}

// ------------- launch -------------
extern "C" void kernel_launch(void* const* d_in, const int* in_sizes, int n_in,
                              void* d_out, int out_size)
{
    const float* x     = (const float*)d_in[0];
    const float* A     = (const float*)d_in[1];
    const float* Bm    = (const float*)d_in[2];
    const float* C     = (const float*)d_in[3];
    const float* D     = (const float*)d_in[4];
    const float* Wsel  = (const float*)d_in[5];
    const float* bsel  = (const float*)d_in[6];
    const float* gamma = (const float*)d_in[7];
    const float* beta  = (const float*)d_in[8];
    float* out = (float*)d_out;

    zeroK<<<(B_*O_ + 255)/256, 256>>>();
    gateK<<<512, 256>>>(x, Wsel, bsel, Bm);
    recK<<<B_, 128>>>(A, gamma, beta);
    selK<<<B_, 128>>>(x, Wsel, bsel);

    int smem = (64*64 + 32*64)*8 + (4*128 + 4*64 + 4*64 + 64)*4;
    cudaFuncSetAttribute(outK, cudaFuncAttributeMaxDynamicSharedMemorySize, smem);
    outK<<<B_*NSEG, 256, smem>>>(x, C, D, out);
    finK<<<1, 256>>>(out);
}

// round 2
// speedup vs baseline: 1.0003x; 1.0003x over previous
#include <cuda_runtime.h>
#include <math.h>

#define B_ 64
#define T_ 2048
#define I_ 64
#define S_ 128
#define O_ 64
#define LN_EPS 1e-5f
#define NSEG 8
#define SEGT (T_/NSEG)

typedef unsigned long long ull;

// ------------- device scratch (no allocs allowed) -------------
__device__ float g_G [B_*T_*S_];   // sigmoid gates
__device__ float g_XB[B_*T_*S_];   // x @ B^T
__device__ float g_H [B_*T_*S_];   // normalized hidden states
__device__ float g_boSum[B_*O_];
__device__ float g_boSsq[B_*O_];
__device__ float g_S1;   // sum of diff norms
__device__ float g_S2;   // sum of norms
__device__ float g_SA;   // sum of sigmoids (selection activity)

// ------------- f32x2 helpers (Blackwell packed FMA) -------------
__device__ __forceinline__ ull pack2(float lo, float hi) {
    ull r; asm("mov.b64 %0,{%1,%2};" : "=l"(r) : "f"(lo), "f"(hi)); return r;
}
__device__ __forceinline__ void unpack2(ull v, float &lo, float &hi) {
    asm("mov.b64 {%0,%1},%2;" : "=f"(lo), "=f"(hi) : "l"(v));
}
__device__ __forceinline__ ull ffma2(ull a, ull b, ull c) {
    ull d; asm("fma.rn.f32x2 %0,%1,%2,%3;" : "=l"(d) : "l"(a), "l"(b), "l"(c)); return d;
}

// ------------- zero accumulators -------------
__global__ void zeroK() {
    int i = blockIdx.x * blockDim.x + threadIdx.x;
    if (i < B_*O_) { g_boSum[i] = 0.f; g_boSsq[i] = 0.f; }
    if (i == 0) { g_S1 = 0.f; g_S2 = 0.f; g_SA = 0.f; }
}

// ------------- kernel 1: precompute gates and x@B^T -------------
// grid 512 blocks x 256 threads; each block handles 256 (b,t) rows.
// threads 0..127 compute gate row (Wsel), 128..255 compute XB row (Bm).
__global__ __launch_bounds__(256) void gateK(
    const float* __restrict__ x, const float* __restrict__ Wsel,
    const float* __restrict__ bsel, const float* __restrict__ Bm)
{
    __shared__ __align__(16) float xs[4][I_];
    int tid = threadIdx.x;
    bool isG = tid < S_;
    int s = isG ? tid : tid - S_;
    const float* wrow = isG ? (Wsel + s*I_) : (Bm + s*I_);
    ull w2[I_/2];
#pragma unroll
    for (int k = 0; k < I_/2; k++) w2[k] = pack2(wrow[2*k], wrow[2*k+1]);
    float bias = isG ? bsel[s] : 0.f;
    int row0 = blockIdx.x * 256;
    for (int g = 0; g < 256; g += 4) {
        {
            int r = tid >> 6, i = tid & 63;
            xs[r][i] = x[(row0 + g + r)*I_ + i];
        }
        __syncthreads();
#pragma unroll
        for (int r = 0; r < 4; r++) {
            const ull* xv = (const ull*)xs[r];
            ull a0 = 0, a1 = 0, a2 = 0, a3 = 0;
#pragma unroll
            for (int k = 0; k < I_/2; k += 4) {
                a0 = ffma2(w2[k+0], xv[k+0], a0);
                a1 = ffma2(w2[k+1], xv[k+1], a1);
                a2 = ffma2(w2[k+2], xv[k+2], a2);
                a3 = ffma2(w2[k+3], xv[k+3], a3);
            }
            float p,q,u,v,e,f,m,n;
            unpack2(a0,p,q); unpack2(a1,u,v); unpack2(a2,e,f); unpack2(a3,m,n);
            float dot = ((p+q)+(u+v)) + ((e+f)+(m+n));
            int row = row0 + g + r;
            if (isG) {
                float z = dot + bias;
                g_G[row*S_ + s] = 1.f / (1.f + __expf(-z));
            } else {
                g_XB[row*S_ + s] = dot;
            }
        }
        __syncthreads();
    }
}

// ------------- kernel 2: sequential recurrence, one CTA per batch -------------
// Lazy-LN trick: A is pre-scaled by gamma; dot runs on raw blended state hb,
// LN statistics (concurrent shfl reduce) enter as scalar corrections.
__global__ __launch_bounds__(128, 1) void recK(
    const float* __restrict__ A, const float* __restrict__ gamma,
    const float* __restrict__ beta)
{
    __shared__ __align__(16) float hbuf[2][S_];
    __shared__ float2 red[4];
    int s = threadIdx.x;
    int b = blockIdx.x;
    int lane = s & 31, warp = s >> 5;

    // A row folded with gamma; constant correction terms
    ull a2[S_/2];
    float agsum = 0.f, ab = 0.f;
    const float* arow = A + s*S_;
#pragma unroll
    for (int k = 0; k < S_/2; k++) {
        float g0 = gamma[2*k], g1 = gamma[2*k+1];
        float v0 = arow[2*k]*g0, v1 = arow[2*k+1]*g1;
        a2[k] = pack2(v0, v1);
        agsum += v0 + v1;
        ab += arow[2*k]*beta[2*k] + arow[2*k+1]*beta[2*k+1];
    }
    float gam_s = gamma[s], bet_s = beta[s];

    hbuf[0][s] = 0.f; hbuf[1][s] = 0.f;
    float hbmine = 0.f;

    const float* Gp  = g_G  + b*T_*S_ + s;
    const float* XBp = g_XB + b*T_*S_ + s;
    float*       Hp  = g_H  + b*T_*S_ + s;

    float gb[4], xb[4];
#pragma unroll
    for (int j = 0; j < 4; j++) { gb[j] = Gp[j*S_]; xb[j] = XBp[j*S_]; }
    __syncthreads();

    int cur = 0;
#pragma unroll 4
    for (int t = 0; t < T_; t++) {
        int slot = t & 3;
        float g = gb[slot], xbv = xb[slot];
        int tp = (t + 4 < T_) ? (t + 4) : (T_ - 1);
        gb[slot] = Gp[tp*S_]; xb[slot] = XBp[tp*S_];

        // concurrent reduction of previous hb (sum, sumsq)
        float s1 = hbmine, s2 = hbmine*hbmine;
#pragma unroll
        for (int off = 16; off > 0; off >>= 1) {
            s1 += __shfl_xor_sync(0xffffffffu, s1, off);
            s2 += __shfl_xor_sync(0xffffffffu, s2, off);
        }
        if (lane == 0) red[warp] = make_float2(s1, s2);

        // dot over raw hb with gamma-folded A
        const ulonglong2* hv = (const ulonglong2*)hbuf[cur];
        ull ac0 = 0, ac1 = 0, ac2 = 0, ac3 = 0;
#pragma unroll
        for (int j = 0; j < S_/4; j += 2) {
            ulonglong2 p = hv[j], q = hv[j+1];
            ac0 = ffma2(a2[2*j+0], p.x, ac0);
            ac1 = ffma2(a2[2*j+1], p.y, ac1);
            ac2 = ffma2(a2[2*j+2], q.x, ac2);
            ac3 = ffma2(a2[2*j+3], q.y, ac3);
        }
        __syncthreads();

        float2 r0 = red[0], r1 = red[1], r2 = red[2], r3 = red[3];
        float sum = (r0.x + r1.x) + (r2.x + r3.x);
        float ssq = (r0.y + r1.y) + (r2.y + r3.y);
        float mu  = sum * (1.f/S_);
        float var = ssq * (1.f/S_) - mu*mu;
        float rin = rsqrtf(var + LN_EPS);

        float hpn;
        if (t > 0) {
            hpn = (hbmine - mu)*rin*gam_s + bet_s;
            Hp[(t-1)*S_] = hpn;            // normalized h_{t-1}
        } else hpn = 0.f;

        float p0,p1,p2,p3,p4,p5,p6,p7;
        unpack2(ac0,p0,p1); unpack2(ac1,p2,p3); unpack2(ac2,p4,p5); unpack2(ac3,p6,p7);
        float dotAg = ((p0+p1)+(p2+p3)) + ((p4+p5)+(p6+p7));
        float abterm = (t > 0) ? ab : 0.f;
        float nextraw = rin*(dotAg - mu*agsum) + abterm + xbv;  // = LN(h_{t-1})@A^T + xb
        float hbnew = g*nextraw + (1.f - g)*hpn;

        hbmine = hbnew;
        hbuf[cur ^ 1][s] = hbnew;
        __syncthreads();
        cur ^= 1;
    }

    // epilogue: normalize and store the final state h_{T-1}
    float s1 = hbmine, s2 = hbmine*hbmine;
#pragma unroll
    for (int off = 16; off > 0; off >>= 1) {
        s1 += __shfl_xor_sync(0xffffffffu, s1, off);
        s2 += __shfl_xor_sync(0xffffffffu, s2, off);
    }
    if (lane == 0) red[warp] = make_float2(s1, s2);
    __syncthreads();
    float2 q0 = red[0], q1 = red[1], q2 = red[2], q3 = red[3];
    float sum = (q0.x + q1.x) + (q2.x + q3.x);
    float ssq = (q0.y + q1.y) + (q2.y + q3.y);
    float mu  = sum * (1.f/S_);
    float var = ssq * (1.f/S_) - mu*mu;
    float rin = rsqrtf(var + LN_EPS);
    Hp[(T_-1)*S_] = (hbmine - mu)*rin*gam_s + bet_s;
}

// ------------- selection activity -------------
__global__ __launch_bounds__(128) void selK(
    const float* __restrict__ x, const float* __restrict__ Wsel,
    const float* __restrict__ bsel)
{
    __shared__ float xm2[2][I_];
    __shared__ float part[4];
    int tid = threadIdx.x, b = blockIdx.x;
    int i = tid & 63, half = tid >> 6;
    const float* xp = x + ((size_t)b*T_ + half*(T_/2))*I_ + i;
    float a0=0,a1=0,a2=0,a3=0;
    for (int t = 0; t < T_/2; t += 4) {
        a0 += xp[(t+0)*I_]; a1 += xp[(t+1)*I_];
        a2 += xp[(t+2)*I_]; a3 += xp[(t+3)*I_];
    }
    xm2[half][i] = (a0+a1)+(a2+a3);
    __syncthreads();
    float acc = bsel[tid];
    const float* w = Wsel + tid*I_;
    const float invT = 1.0f/(float)T_;
#pragma unroll 8
    for (int k = 0; k < I_; k++) acc += (xm2[0][k] + xm2[1][k]) * invT * w[k];
    float sg = 1.f/(1.f + __expf(-acc));
#pragma unroll
    for (int off = 16; off > 0; off >>= 1) sg += __shfl_xor_sync(0xffffffffu, sg, off);
    if ((tid & 31) == 0) part[tid >> 5] = sg;
    __syncthreads();
    if (tid == 0) atomicAdd(&g_SA, (part[0]+part[1]) + (part[2]+part[3]));
}

// ------------- kernel 3: Y = H@C^T + x@D^T plus statistics -------------
// grid (B_*NSEG) x 256 threads; dynamic smem.
__global__ void outK(const float* __restrict__ x, const float* __restrict__ C,
                     const float* __restrict__ D, float* __restrict__ out)
{
    extern __shared__ __align__(16) char smraw[];
    ull*   Cp = (ull*)smraw;            // [64][64] pairs along s
    ull*   Dp = Cp + 64*64;             // [32][64] pairs along i
    float* Hs = (float*)(Dp + 32*64);   // [4][128]
    float* xs = Hs + 4*128;             // [4][64]
    float* Ys = xs + 4*64;              // [4][64]
    float* yp = Ys + 4*64;              // [64] previous row

    int tid = threadIdx.x;
    int b = blockIdx.x >> 3;
    int seg = blockIdx.x & 7;
    int tl = tid >> 6, o = tid & 63;
    int t0 = seg * SEGT;

    for (int idx = tid; idx < 64*64; idx += 256) {
        int k = idx >> 6, oo = idx & 63;
        Cp[idx] = pack2(C[oo*S_ + 2*k], C[oo*S_ + 2*k + 1]);
    }
    for (int idx = tid; idx < 32*64; idx += 256) {
        int k = idx >> 6, oo = idx & 63;
        Dp[idx] = pack2(D[oo*I_ + 2*k], D[oo*I_ + 2*k + 1]);
    }
    if (tid < 64) yp[tid] = 0.f;
    __syncthreads();

    // boundary row t0-1 (recomputed so diffs cross segment borders)
    if (seg > 0) {
        if (tid < 128) Hs[tid] = g_H[((size_t)b*T_ + (t0-1))*S_ + tid];
        if (tid >= 128 && tid < 192) xs[tid-128] = x[((size_t)b*T_ + (t0-1))*I_ + (tid-128)];
        __syncthreads();
        if (tid < 64) {
            const ull* hv = (const ull*)Hs;
            ull ac0 = 0, ac1 = 0;
#pragma unroll
            for (int k = 0; k < 64; k += 2) {
                ac0 = ffma2(hv[k],   Cp[k*64 + tid],     ac0);
                ac1 = ffma2(hv[k+1], Cp[(k+1)*64 + tid], ac1);
            }
            const ull* xv = (const ull*)xs;
#pragma unroll
            for (int k = 0; k < 32; k += 2) {
                ac0 = ffma2(xv[k],   Dp[k*64 + tid],     ac0);
                ac1 = ffma2(xv[k+1], Dp[(k+1)*64 + tid], ac1);
            }
            float u,v,e,f; unpack2(ac0,u,v); unpack2(ac1,e,f);
            yp[tid] = (u+v)+(e+f);
        }
    }
    __syncthreads();

    float boS = 0.f, boQ = 0.f;       // per-(b,o) partials over this thread's t's
    float nrmAcc = 0.f, difAcc = 0.f; // only meaningful on (warp<4, lane0)
    int w = tid >> 5, lane = tid & 31;

    for (int g = 0; g < SEGT/4; g++) {
        int tbase = t0 + g*4;
        Hs[tid]       = g_H[((size_t)b*T_ + tbase + (tid >> 7))    *S_ + (tid & 127)];
        Hs[tid + 256] = g_H[((size_t)b*T_ + tbase + 2 + (tid >> 7))*S_ + (tid & 127)];
        xs[tid]       = x  [((size_t)b*T_ + tbase + (tid >> 6))    *I_ + (tid & 63)];
        __syncthreads();

        float y;
        {
            const ull* hv = (const ull*)(Hs + tl*128);
            ull ac0 = 0, ac1 = 0;
#pragma unroll
            for (int k = 0; k < 64; k += 2) {
                ac0 = ffma2(hv[k],   Cp[k*64 + o],     ac0);
                ac1 = ffma2(hv[k+1], Cp[(k+1)*64 + o], ac1);
            }
            const ull* xv = (const ull*)(xs + tl*64);
#pragma unroll
            for (int k = 0; k < 32; k += 2) {
                ac0 = ffma2(xv[k],   Dp[k*64 + o],     ac0);
                ac1 = ffma2(xv[k+1], Dp[(k+1)*64 + o], ac1);
            }
            float u,v,e,f; unpack2(ac0,u,v); unpack2(ac1,e,f);
            y = (u+v)+(e+f);
        }
        Ys[tl*64 + o] = y;
        boS += y; boQ += y*y;
        if (tbase + tl == T_ - 1) out[b*O_ + o] = y;   // final[b, o]
        __syncthreads();

        if (w < 4) {   // warps 0..3 reduce row norms and diff norms
            float y0 = Ys[w*64 + lane], y1 = Ys[w*64 + lane + 32];
            float p0, p1;
            if (w == 0) { p0 = yp[lane]; p1 = yp[lane + 32]; }
            else        { p0 = Ys[(w-1)*64 + lane]; p1 = Ys[(w-1)*64 + lane + 32]; }
            float sn = y0*y0 + y1*y1;
            float d0 = y0 - p0, d1 = y1 - p1;
            float dn = d0*d0 + d1*d1;
#pragma unroll
            for (int off = 16; off > 0; off >>= 1) {
                sn += __shfl_xor_sync(0xffffffffu, sn, off);
                dn += __shfl_xor_sync(0xffffffffu, dn, off);
            }
            if (lane == 0) {
                nrmAcc += sqrtf(sn);
                if (tbase + w > 0) difAcc += sqrtf(dn);
            }
        }
        __syncthreads();
        if (tid < 64) yp[tid] = Ys[3*64 + tid];
        __syncthreads();
    }

    if (w < 4 && lane == 0) {
        atomicAdd(&g_S2, nrmAcc);
        atomicAdd(&g_S1, difAcc);
    }
    // combine per-(b,o) partials across the 4 tl groups
    __syncthreads();
    Ys[tid] = boS;
    __syncthreads();
    if (tl == 0) atomicAdd(&g_boSum[b*64 + o], (Ys[o] + Ys[64+o]) + (Ys[128+o] + Ys[192+o]));
    __syncthreads();
    Ys[tid] = boQ;
    __syncthreads();
    if (tl == 0) atomicAdd(&g_boSsq[b*64 + o], (Ys[o] + Ys[64+o]) + (Ys[128+o] + Ys[192+o]));
}

// ------------- finalize scalars -------------
__global__ void finK(float* __restrict__ out)
{
    __shared__ float part[8];
    int tid = threadIdx.x;
    float acc = 0.f;
    for (int idx = tid; idx < B_*O_; idx += 256) {
        float sum = g_boSum[idx], ssq = g_boSsq[idx];
        float var = (ssq - sum*sum*(1.f/T_)) * (1.f/(T_ - 1));
        acc += sqrtf(fmaxf(var, 0.f));
    }
#pragma unroll
    for (int off = 16; off > 0; off >>= 1) acc += __shfl_xor_sync(0xffffffffu, acc, off);
    if ((tid & 31) == 0) part[tid >> 5] = acc;
    __syncthreads();
    if (tid == 0) {
        float tot = 0.f;
#pragma unroll
        for (int k = 0; k < 8; k++) tot += part[k];
        out[4096] = 1.f / (1.f + g_S1 / (float)(B_*(T_-1)));
        out[4097] = g_S2 / (float)(B_*T_);
        out[4098] = g_SA / (float)(B_*S_);
        out[4099] = tot  / (float)(B_*O_);
    }
}

// ------------- launch -------------
extern "C" void kernel_launch(void* const* d_in, const int* in_sizes, int n_in,
                              void* d_out, int out_size)
{
    const float* x     = (const float*)d_in[0];
    const float* A     = (const float*)d_in[1];
    const float* Bm    = (const float*)d_in[2];
    const float* C     = (const float*)d_in[3];
    const float* D     = (const float*)d_in[4];
    const float* Wsel  = (const float*)d_in[5];
    const float* bsel  = (const float*)d_in[6];
    const float* gamma = (const float*)d_in[7];
    const float* beta  = (const float*)d_in[8];
    float* out = (float*)d_out;

    zeroK<<<(B_*O_ + 255)/256, 256>>>();
    gateK<<<512, 256>>>(x, Wsel, bsel, Bm);
    recK<<<B_, 128>>>(A, gamma, beta);
    selK<<<B_, 128>>>(x, Wsel, bsel);

    int smem = (64*64 + 32*64)*8 + (4*128 + 4*64 + 4*64 + 64)*4;
    cudaFuncSetAttribute(outK, cudaFuncAttributeMaxDynamicSharedMemorySize, smem);
    outK<<<B_*NSEG, 256, smem>>>(x, C, D, out);
    finK<<<1, 256>>>(out);
}

// round 3
// speedup vs baseline: 1.1773x; 1.1770x over previous
#include <cuda_runtime.h>
#include <math.h>

#define B_ 64
#define T_ 2048
#define I_ 64
#define S_ 128
#define O_ 64
#define LN_EPS 1e-5f
#define NSEG 8
#define SEGT (T_/NSEG)
#define TP 2052

typedef unsigned long long ull;

__device__ float g_GX[2ull*B_*TP*S_];  // packed (gate, x@B^T)
__device__ float g_H [B_*T_*S_];
__device__ float g_xsum[B_*I_];
__device__ float g_boSum[B_*O_];
__device__ float g_boSsq[B_*O_];
__device__ float g_S1, g_S2, g_SA;

__device__ __forceinline__ ull pack2(float lo, float hi) {
    ull r; asm("mov.b64 %0,{%1,%2};" : "=l"(r) : "f"(lo), "f"(hi)); return r;
}
__device__ __forceinline__ void unpack2(ull v, float &lo, float &hi) {
    asm("mov.b64 {%0,%1},%2;" : "=f"(lo), "=f"(hi) : "l"(v));
}
__device__ __forceinline__ ull ffma2(ull a, ull b, ull c) {
    ull d; asm("fma.rn.f32x2 %0,%1,%2,%3;" : "=l"(d) : "l"(a), "l"(b), "l"(c)); return d;
}

__global__ void zeroK() {
    int i = blockIdx.x * blockDim.x + threadIdx.x;
    if (i < B_*O_) { g_boSum[i] = 0.f; g_boSsq[i] = 0.f; }
    if (i < B_*I_) g_xsum[i] = 0.f;
    if (i == 0) { g_S1 = 0.f; g_S2 = 0.f; g_SA = 0.f; }
}

// gates + x@B^T packed, plus x column sums. grid = B_*8
__global__ __launch_bounds__(256) void gateK(
    const float* __restrict__ x, const float* __restrict__ Wsel,
    const float* __restrict__ bsel, const float* __restrict__ Bm)
{
    __shared__ __align__(16) float xs[4][I_];
    __shared__ __align__(16) float ysm[4][2*S_];
    int tid = threadIdx.x;
    bool isG = tid < S_;
    int s = isG ? tid : tid - S_;
    const float* wrow = isG ? (Wsel + s*I_) : (Bm + s*I_);
    ull w2[I_/2];
#pragma unroll
    for (int k = 0; k < I_/2; k++) w2[k] = pack2(wrow[2*k], wrow[2*k+1]);
    float bias = isG ? bsel[s] : 0.f;

    int b  = blockIdx.x >> 3;
    int t0 = (blockIdx.x & 7) * 256;
    const float* xrow = x + ((size_t)b*T_ + t0)*I_;
    float2* outp = ((float2*)g_GX) + (size_t)b*TP*S_;
    float xacc = 0.f;

    for (int g = 0; g < 256; g += 4) {
        { int r = tid >> 6, i = tid & 63;
          xs[r][i] = xrow[(g + r)*I_ + i]; }
        __syncthreads();
#pragma unroll
        for (int r = 0; r < 4; r++) {
            const ull* xv = (const ull*)xs[r];
            ull a0 = 0, a1 = 0, a2 = 0, a3 = 0;
#pragma unroll
            for (int k = 0; k < I_/2; k += 4) {
                a0 = ffma2(w2[k+0], xv[k+0], a0);
                a1 = ffma2(w2[k+1], xv[k+1], a1);
                a2 = ffma2(w2[k+2], xv[k+2], a2);
                a3 = ffma2(w2[k+3], xv[k+3], a3);
            }
            float p,q,u,v,e,f,m,n;
            unpack2(a0,p,q); unpack2(a1,u,v); unpack2(a2,e,f); unpack2(a3,m,n);
            float dot = ((p+q)+(u+v)) + ((e+f)+(m+n));
            if (isG) ysm[r][2*s]     = 1.f / (1.f + __expf(-(dot + bias)));
            else     ysm[r][2*s + 1] = dot;
        }
        if (tid < 64) xacc += (xs[0][tid]+xs[1][tid]) + (xs[2][tid]+xs[3][tid]);
        __syncthreads();
        const float2* fy = (const float2*)ysm;
#pragma unroll
        for (int rr = 0; rr < 2; rr++) {
            int idx = tid + rr*256;
            outp[(size_t)(t0 + g + (idx >> 7))*S_ + (idx & 127)] = fy[idx];
        }
    }
    if (tid < 64) atomicAdd(&g_xsum[b*64 + tid], xacc);
}

__global__ __launch_bounds__(128) void selFin(
    const float* __restrict__ Wsel, const float* __restrict__ bsel)
{
    __shared__ float part[4];
    int tid = threadIdx.x, b = blockIdx.x;
    float acc = bsel[tid];
    const float invT = 1.0f/(float)T_;
    const float* w  = Wsel + tid*I_;
    const float* xm = g_xsum + b*I_;
#pragma unroll 8
    for (int k = 0; k < I_; k++) acc += xm[k]*invT*w[k];
    float sg = 1.f/(1.f + __expf(-acc));
#pragma unroll
    for (int off = 16; off > 0; off >>= 1) sg += __shfl_xor_sync(0xffffffffu, sg, off);
    if ((tid & 31) == 0) part[tid >> 5] = sg;
    __syncthreads();
    if (tid == 0) atomicAdd(&g_SA, (part[0]+part[1]) + (part[2]+part[3]));
}

// recurrence: 256 threads, warp-specialized halves
__global__ __launch_bounds__(256, 1) void recK(
    const float* __restrict__ A, const float* __restrict__ gamma,
    const float* __restrict__ beta)
{
    __shared__ __align__(16) float hbuf[2][136];
    __shared__ __align__(16) float dpart[S_];
    __shared__ __align__(16) float2 red[4];
    int tid = threadIdx.x, b = blockIdx.x;
    int s = tid & 127, q = tid >> 7;
    int wid = tid >> 5, lane = tid & 31;
    int hoff = s + ((s & 64) >> 4);

    float agsum = 0.f, ab = 0.f;
    float gam_s = gamma[s], bet_s = beta[s];
    if (!q) {
        const float* ar = A + s*S_;
#pragma unroll 16
        for (int k = 0; k < S_; k++) {
            agsum += ar[k]*gamma[k]; ab += ar[k]*beta[k];
        }
    }
    ull a2[32];
    {
        const float* ar = A + s*S_ + q*64;
        const float* gm = gamma + q*64;
#pragma unroll
        for (int k = 0; k < 32; k++)
            a2[k] = pack2(ar[2*k]*gm[2*k], ar[2*k+1]*gm[2*k+1]);
    }

    if (tid < 136) { hbuf[0][tid] = 0.f; hbuf[1][tid] = 0.f; }
    if (tid < S_)  dpart[tid] = 0.f;
    if (tid < 4)   red[tid] = make_float2(0.f, 0.f);

    const float2* GX = ((const float2*)g_GX) + (size_t)b*TP*S_ + s;
    float* Hp = g_H + (size_t)b*T_*S_ + s;
    float2 gx[4];
    if (!q) {
#pragma unroll
        for (int j = 0; j < 4; j++) gx[j] = GX[(size_t)j*S_];
    }
    float hbmine = 0.f;
    __syncthreads();

    int cur = 0;
#pragma unroll 4
    for (int t = 0; t < T_; t++) {
        float s1 = 0.f, s2 = 0.f;
        float2 gxv = make_float2(0.f, 0.f);
        if (q) {
            float hm = hbuf[cur][hoff];
            s1 = hm; s2 = hm*hm;
#pragma unroll
            for (int off = 16; off > 0; off >>= 1) {
                s1 += __shfl_xor_sync(0xffffffffu, s1, off);
                s2 += __shfl_xor_sync(0xffffffffu, s2, off);
            }
        } else {
            gxv = gx[t & 3];
            gx[t & 3] = GX[(size_t)(t + 4)*S_];
        }

        const ulonglong2* hv = (const ulonglong2*)(&hbuf[cur][q*68]);
        ull ac0 = 0, ac1 = 0, ac2 = 0, ac3 = 0;
#pragma unroll
        for (int i = 0; i < 16; i += 4) {
            ulonglong2 p = hv[i], r = hv[i+1], u = hv[i+2], v = hv[i+3];
            ac0 = ffma2(a2[2*i+0], p.x, ac0); ac1 = ffma2(a2[2*i+1], p.y, ac1);
            ac2 = ffma2(a2[2*i+2], r.x, ac2); ac3 = ffma2(a2[2*i+3], r.y, ac3);
            ac0 = ffma2(a2[2*i+4], u.x, ac0); ac1 = ffma2(a2[2*i+5], u.y, ac1);
            ac2 = ffma2(a2[2*i+6], v.x, ac2); ac3 = ffma2(a2[2*i+7], v.y, ac3);
        }
        float p0,p1,p2,p3,p4,p5,p6,p7;
        unpack2(ac0,p0,p1); unpack2(ac1,p2,p3); unpack2(ac2,p4,p5); unpack2(ac3,p6,p7);
        float dmine = ((p0+p1)+(p2+p3)) + ((p4+p5)+(p6+p7));

        if (q) {
            dpart[s] = dmine;
            if (lane == 0) red[wid - 4] = make_float2(s1, s2);
        }
        __syncthreads();

        if (!q) {
            float4 r01 = ((const float4*)red)[0];
            float4 r23 = ((const float4*)red)[1];
            float sum = (r01.x + r01.z) + (r23.x + r23.z);
            float ssq = (r01.y + r01.w) + (r23.y + r23.w);
            float mu  = sum * (1.f/S_);
            float var = ssq * (1.f/S_) - mu*mu;
            float rin = rsqrtf(var + LN_EPS);
            float dfull = dmine + dpart[s];
            float hpn, abterm;
            if (t > 0) {
                hpn = (hbmine - mu)*rin*gam_s + bet_s;
                Hp[(size_t)(t-1)*S_] = hpn;
                abterm = ab;
            } else { hpn = 0.f; abterm = 0.f; }
            float nextraw = rin*(dfull - mu*agsum) + abterm + gxv.y;
            float hb = gxv.x*nextraw + (1.f - gxv.x)*hpn;
            hbmine = hb;
            hbuf[cur ^ 1][hoff] = hb;
        }
        __syncthreads();
        cur ^= 1;
    }

    if (q) {
        float hm = hbuf[cur][hoff];
        float s1 = hm, s2 = hm*hm;
#pragma unroll
        for (int off = 16; off > 0; off >>= 1) {
            s1 += __shfl_xor_sync(0xffffffffu, s1, off);
            s2 += __shfl_xor_sync(0xffffffffu, s2, off);
        }
        if (lane == 0) red[wid - 4] = make_float2(s1, s2);
    }
    __syncthreads();
    if (!q) {
        float4 r01 = ((const float4*)red)[0];
        float4 r23 = ((const float4*)red)[1];
        float sum = (r01.x + r01.z) + (r23.x + r23.z);
        float ssq = (r01.y + r01.w) + (r23.y + r23.w);
        float mu  = sum * (1.f/S_);
        float var = ssq * (1.f/S_) - mu*mu;
        float rin = rsqrtf(var + LN_EPS);
        Hp[(size_t)(T_-1)*S_] = (hbmine - mu)*rin*gam_s + bet_s;
    }
}

// Y = H@C^T + x@D^T plus statistics
__global__ void outK(const float* __restrict__ x, const float* __restrict__ C,
                     const float* __restrict__ D, float* __restrict__ out)
{
    extern __shared__ __align__(16) char smraw[];
    ull*   Cp = (ull*)smraw;
    ull*   Dp = Cp + 64*64;
    float* Hs = (float*)(Dp + 32*64);
    float* xs = Hs + 4*128;
    float* Ys = xs + 4*64;
    float* yp = Ys + 4*64;

    int tid = threadIdx.x;
    int b = blockIdx.x >> 3;
    int seg = blockIdx.x & 7;
    int tl = tid >> 6, o = tid & 63;
    int t0 = seg * SEGT;

    for (int idx = tid; idx < 64*64; idx += 256) {
        int k = idx >> 6, oo = idx & 63;
        Cp[idx] = pack2(C[oo*S_ + 2*k], C[oo*S_ + 2*k + 1]);
    }
    for (int idx = tid; idx < 32*64; idx += 256) {
        int k = idx >> 6, oo = idx & 63;
        Dp[idx] = pack2(D[oo*I_ + 2*k], D[oo*I_ + 2*k + 1]);
    }
    if (tid < 64) yp[tid] = 0.f;
    __syncthreads();

    if (seg > 0) {
        if (tid < 128) Hs[tid] = g_H[((size_t)b*T_ + (t0-1))*S_ + tid];
        if (tid >= 128 && tid < 192) xs[tid-128] = x[((size_t)b*T_ + (t0-1))*I_ + (tid-128)];
        __syncthreads();
        if (tid < 64) {
            const ull* hv = (const ull*)Hs;
            ull ac0 = 0, ac1 = 0;
#pragma unroll
            for (int k = 0; k < 64; k += 2) {
                ac0 = ffma2(hv[k],   Cp[k*64 + tid],     ac0);
                ac1 = ffma2(hv[k+1], Cp[(k+1)*64 + tid], ac1);
            }
            const ull* xv = (const ull*)xs;
#pragma unroll
            for (int k = 0; k < 32; k += 2) {
                ac0 = ffma2(xv[k],   Dp[k*64 + tid],     ac0);
                ac1 = ffma2(xv[k+1], Dp[(k+1)*64 + tid], ac1);
            }
            float u,v,e,f; unpack2(ac0,u,v); unpack2(ac1,e,f);
            yp[tid] = (u+v)+(e+f);
        }
    }
    __syncthreads();

    float boS = 0.f, boQ = 0.f;
    float nrmAcc = 0.f, difAcc = 0.f;
    int w = tid >> 5, lane = tid & 31;

    for (int g = 0; g < SEGT/4; g++) {
        int tbase = t0 + g*4;
        Hs[tid]       = g_H[((size_t)b*T_ + tbase + (tid >> 7))    *S_ + (tid & 127)];
        Hs[tid + 256] = g_H[((size_t)b*T_ + tbase + 2 + (tid >> 7))*S_ + (tid & 127)];
        xs[tid]       = x  [((size_t)b*T_ + tbase + (tid >> 6))    *I_ + (tid & 63)];
        __syncthreads();

        float y;
        {
            const ull* hv = (const ull*)(Hs + tl*128);
            ull ac0 = 0, ac1 = 0;
#pragma unroll
            for (int k = 0; k < 64; k += 2) {
                ac0 = ffma2(hv[k],   Cp[k*64 + o],     ac0);
                ac1 = ffma2(hv[k+1], Cp[(k+1)*64 + o], ac1);
            }
            const ull* xv = (const ull*)(xs + tl*64);
#pragma unroll
            for (int k = 0; k < 32; k += 2) {
                ac0 = ffma2(xv[k],   Dp[k*64 + o],     ac0);
                ac1 = ffma2(xv[k+1], Dp[(k+1)*64 + o], ac1);
            }
            float u,v,e,f; unpack2(ac0,u,v); unpack2(ac1,e,f);
            y = (u+v)+(e+f);
        }
        Ys[tl*64 + o] = y;
        boS += y; boQ += y*y;
        if (tbase + tl == T_ - 1) out[b*O_ + o] = y;
        __syncthreads();

        if (w < 4) {
            float y0 = Ys[w*64 + lane], y1 = Ys[w*64 + lane + 32];
            float p0, p1;
            if (w == 0) { p0 = yp[lane]; p1 = yp[lane + 32]; }
            else        { p0 = Ys[(w-1)*64 + lane]; p1 = Ys[(w-1)*64 + lane + 32]; }
            float sn = y0*y0 + y1*y1;
            float d0 = y0 - p0, d1 = y1 - p1;
            float dn = d0*d0 + d1*d1;
#pragma unroll
            for (int off = 16; off > 0; off >>= 1) {
                sn += __shfl_xor_sync(0xffffffffu, sn, off);
                dn += __shfl_xor_sync(0xffffffffu, dn, off);
            }
            if (lane == 0) {
                nrmAcc += sqrtf(sn);
                if (tbase + w > 0) difAcc += sqrtf(dn);
            }
        }
        __syncthreads();
        if (tid < 64) yp[tid] = Ys[3*64 + tid];
        __syncthreads();
    }

    if (w < 4 && lane == 0) {
        atomicAdd(&g_S2, nrmAcc);
        atomicAdd(&g_S1, difAcc);
    }
    __syncthreads();
    Ys[tid] = boS;
    __syncthreads();
    if (tl == 0) atomicAdd(&g_boSum[b*64 + o], (Ys[o] + Ys[64+o]) + (Ys[128+o] + Ys[192+o]));
    __syncthreads();
    Ys[tid] = boQ;
    __syncthreads();
    if (tl == 0) atomicAdd(&g_boSsq[b*64 + o], (Ys[o] + Ys[64+o]) + (Ys[128+o] + Ys[192+o]));
}

__global__ void finK(float* __restrict__ out)
{
    __shared__ float part[8];
    int tid = threadIdx.x;
    float acc = 0.f;
    for (int idx = tid; idx < B_*O_; idx += 256) {
        float sum = g_boSum[idx], ssq = g_boSsq[idx];
        float var = (ssq - sum*sum*(1.f/T_)) * (1.f/(T_ - 1));
        acc += sqrtf(fmaxf(var, 0.f));
    }
#pragma unroll
    for (int off = 16; off > 0; off >>= 1) acc += __shfl_xor_sync(0xffffffffu, acc, off);
    if ((tid & 31) == 0) part[tid >> 5] = acc;
    __syncthreads();
    if (tid == 0) {
        float tot = 0.f;
#pragma unroll
        for (int k = 0; k < 8; k++) tot += part[k];
        out[4096] = 1.f / (1.f + g_S1 / (float)(B_*(T_-1)));
        out[4097] = g_S2 / (float)(B_*T_);
        out[4098] = g_SA / (float)(B_*S_);
        out[4099] = tot  / (float)(B_*O_);
    }
}

extern "C" void kernel_launch(void* const* d_in, const int* in_sizes, int n_in,
                              void* d_out, int out_size)
{
    const float* x     = (const float*)d_in[0];
    const float* A     = (const float*)d_in[1];
    const float* Bm    = (const float*)d_in[2];
    const float* C     = (const float*)d_in[3];
    const float* D     = (const float*)d_in[4];
    const float* Wsel  = (const float*)d_in[5];
    const float* bsel  = (const float*)d_in[6];
    const float* gamma = (const float*)d_in[7];
    const float* beta  = (const float*)d_in[8];
    float* out = (float*)d_out;

    zeroK<<<(B_*O_ + 255)/256, 256>>>();
    gateK<<<B_*8, 256>>>(x, Wsel, bsel, Bm);
    recK<<<B_, 256>>>(A, gamma, beta);
    selFin<<<B_, 128>>>(Wsel, bsel);

    int smem = (64*64 + 32*64)*8 + (4*128 + 4*64 + 4*64 + 64)*4;
    cudaFuncSetAttribute(outK, cudaFuncAttributeMaxDynamicSharedMemorySize, smem);
    outK<<<B_*NSEG, 256, smem>>>(x, C, D, out);
    finK<<<1, 256>>>(out);
}